// round 1
// baseline (speedup 1.0000x reference)
#include <cuda_runtime.h>

#define SEQ 4096
#define TPB 256
#define TOK_PER_T (SEQ / TPB)   // 16 tokens per thread

__global__ __launch_bounds__(TPB, 8)
void tlc_kernel(const int* __restrict__ tok,
                const float* __restrict__ table,
                float* __restrict__ out)
{
    const int row = blockIdx.x;
    const int* t = tok + (size_t)row * SEQ;
    const int tid = threadIdx.x;

    // ---- Phase 1: load my contiguous 16-token chunk (4 x int4, coalesced across unroll)
    int arr[TOK_PER_T];
    const int4* t4 = reinterpret_cast<const int4*>(t) + tid * (TOK_PER_T / 4);
    #pragma unroll
    for (int i = 0; i < TOK_PER_T / 4; i++) {
        int4 v = t4[i];
        arr[i * 4 + 0] = v.x; arr[i * 4 + 1] = v.y;
        arr[i * 4 + 2] = v.z; arr[i * 4 + 3] = v.w;
    }

    __shared__ int sFirst[TPB];
    __shared__ int sScan[TPB];
    sFirst[tid] = arr[0];

    // per-chunk last tag (tags are tokens 46..48 -> values 0..2), -1 if none
    int lastTag = -1;
    #pragma unroll
    for (int i = 0; i < TOK_PER_T; i++) {
        int c = arr[i];
        if ((unsigned)(c - 46) < 3u) lastTag = c - 46;
    }
    sScan[tid] = lastTag;
    __syncthreads();

    // token that follows my chunk (for the bigram straddling the boundary).
    // Last chunk: position SEQ-1 is never a valid 'cur' -> impossible sentinel.
    const int nextFirst = (tid + 1 < TPB) ? sFirst[tid + 1] : -1000000;

    // ---- Phase 2: inclusive Hillis-Steele scan, combine(a,b) = (b>=0 ? b : a)
    #pragma unroll
    for (int off = 1; off < TPB; off <<= 1) {
        int val  = sScan[tid];
        int prev = (tid >= off) ? sScan[tid - off] : -1;
        __syncthreads();
        sScan[tid] = (val >= 0) ? val : prev;
        __syncthreads();
    }
    int tag = (tid > 0) ? sScan[tid - 1] : -1;   // exclusive carry into my chunk

    // query tag (clipped) and role-match masks
    const int qtok = __ldg(&t[SEQ - 1]);
    const int qtag = min(max(qtok - 46, 0), 2);

    unsigned maskA = 0, maskB = 0, maskC = 0;
    #pragma unroll
    for (int i = 0; i < TOK_PER_T; i++) {
        int c = arr[i];
        if ((unsigned)(c - 46) < 3u) tag = c - 46;          // tag at pos p applies to p itself
        int n = (i + 1 < TOK_PER_T) ? arr[i + 1] : nextFirst;
        if (tag == qtag) {                                   // tag==-1 never equals qtag in [0,2]
            if (c == 3 && (unsigned)(n - 22) < 8u) maskA |= 1u << (n - 22);
            if (c == 4 && (unsigned)(n - 30) < 8u) maskB |= 1u << (n - 30);
            if (c == 5 && (unsigned)(n - 38) < 8u) maskC |= 1u << (n - 38);
        }
    }

    // ---- Phase 3: reduce masks, epilogue on thread 0
    maskA = __reduce_or_sync(0xffffffffu, maskA);
    maskB = __reduce_or_sync(0xffffffffu, maskB);
    maskC = __reduce_or_sync(0xffffffffu, maskC);

    __shared__ unsigned sA[TPB / 32], sB[TPB / 32], sC[TPB / 32];
    const int wid = tid >> 5;
    if ((tid & 31) == 0) { sA[wid] = maskA; sB[wid] = maskB; sC[wid] = maskC; }
    __syncthreads();

    if (tid == 0) {
        unsigned mA = 0, mB = 0, mC = 0;
        #pragma unroll
        for (int w = 0; w < TPB / 32; w++) { mA |= sA[w]; mB |= sB[w]; mC |= sC[w]; }

        // argmax of a 0/1 vector = first set bit, or 0 if empty (JAX argmax semantics)
        const int a = mA ? (__ffs(mA) - 1) : 0;
        const int b = mB ? (__ffs(mB) - 1) : 0;
        const int c = mC ? (__ffs(mC) - 1) : 0;

        const int task = min(max(__ldg(&t[1]) - 49, 0), 3);

        float o[8];
        if (task == 3) {
            const float* tp = table + (((a * 8 + b) * 8 + c) * 8);
            #pragma unroll
            for (int k = 0; k < 8; k++) o[k] = __ldg(&tp[k]);
        } else {
            int idx;
            if (task == 0)      idx = a;                                   // copy
            else if (task == 1) idx = (a + 2 * b + 3 * c) & 7;             // affine
            else                idx = (a * (b + 1) + c * ((a ^ b) + 1)) & 7; // gate
            #pragma unroll
            for (int k = 0; k < 8; k++) o[k] = (k == idx) ? 12.0f : 0.0f;
        }

        float4* o4 = reinterpret_cast<float4*>(out + (size_t)row * 8);
        o4[0] = make_float4(o[0], o[1], o[2], o[3]);
        o4[1] = make_float4(o[4], o[5], o[6], o[7]);
    }
}

extern "C" void kernel_launch(void* const* d_in, const int* in_sizes, int n_in,
                              void* d_out, int out_size)
{
    const int* tok     = (const int*)d_in[0];     // token_ids [B, 4096] int32
    const float* table = (const float*)d_in[1];   // lookup_table [8,8,8,8] f32
    float* out         = (float*)d_out;           // [B, 8] f32

    const int B = in_sizes[0] / SEQ;
    tlc_kernel<<<B, TPB>>>(tok, table, out);
}

// round 3
// speedup vs baseline: 1.4707x; 1.4707x over previous
#include <cuda_runtime.h>

#define SEQ 4096
#define TPB 256
#define TOK_PER_T 16
#define NWARP (TPB / 32)

__global__ __launch_bounds__(TPB, 8)
void tlc_kernel(const int* __restrict__ tok,
                const float* __restrict__ table,
                float* __restrict__ out)
{
    const int row  = blockIdx.x;
    const int* t   = tok + (size_t)row * SEQ;
    const int tid  = threadIdx.x;
    const int lane = tid & 31;
    const int wid  = tid >> 5;

    // ---- load my contiguous 16-token chunk (4 x int4)
    int arr[TOK_PER_T];
    const int4* t4 = reinterpret_cast<const int4*>(t) + tid * 4;
    #pragma unroll
    for (int i = 0; i < 4; i++) {
        int4 v = t4[i];
        arr[4*i+0] = v.x; arr[4*i+1] = v.y;
        arr[4*i+2] = v.z; arr[4*i+3] = v.w;
    }

    __shared__ int      sFirst[TPB];
    __shared__ int      sW[NWARP];
    __shared__ unsigned sM[NWARP];
    __shared__ int      sQ[2];       // [0]=last token of row, [1]=t[1]

    sFirst[tid] = arr[0];
    if (tid == TPB - 1) sQ[0] = arr[TOK_PER_T - 1];
    if (tid == 0)       sQ[1] = arr[1];

    // per-chunk last tag (tokens 46..48 -> 0..2), -1 if none
    int lastTag = -1;
    #pragma unroll
    for (int i = 0; i < TOK_PER_T; i++) {
        unsigned tt = (unsigned)(arr[i] - 46);
        if (tt < 3u) lastTag = (int)tt;
    }

    // ---- warp-level inclusive scan, combine(a,b) = (b>=0 ? b : a)
    int inc = lastTag;
    #pragma unroll
    for (int off = 1; off < 32; off <<= 1) {
        int p = __shfl_up_sync(0xffffffffu, inc, off);
        if (lane >= off && inc < 0) inc = p;
    }
    if (lane == 31) sW[wid] = inc;
    __syncthreads();   // covers sFirst, sQ, sW

    // exclusive cross-warp prefix (latest non-negative among earlier warps)
    int wpre = -1;
    #pragma unroll
    for (int w = 0; w < NWARP; w++) {
        int v = sW[w];
        if (w < wid && v >= 0) wpre = v;
    }
    int excl = __shfl_up_sync(0xffffffffu, inc, 1);
    if (lane == 0) excl = -1;
    int tag = (excl >= 0) ? excl : wpre;   // carry into my chunk

    const int nextFirst = (tid + 1 < TPB) ? sFirst[tid + 1] : -1000000;
    const int qtag = min(max(sQ[0] - 46, 0), 2);

    // ---- fused per-token loop: tag update + single-mask bigram match
    // value ranges are contiguous (A:22-29, B:30-37, C:38-45) so bit u = n-22
    // encodes (role,value); role consistency is (c-3) == (u>>3).
    unsigned mask = 0;
    #pragma unroll
    for (int i = 0; i < TOK_PER_T; i++) {
        int c = arr[i];
        unsigned tt = (unsigned)(c - 46);
        if (tt < 3u) tag = (int)tt;                 // tag at pos p applies at p
        int n = (i + 1 < TOK_PER_T) ? arr[i + 1] : nextFirst;
        unsigned u = (unsigned)(n - 22);
        if (u < 24u && (unsigned)(c - 3) == (u >> 3) && tag == qtag)
            mask |= 1u << u;
    }

    // ---- reduce mask across block
    mask = __reduce_or_sync(0xffffffffu, mask);
    if (lane == 0) sM[wid] = mask;
    __syncthreads();

    if (tid == 0) {
        unsigned m = 0;
        #pragma unroll
        for (int w = 0; w < NWARP; w++) m |= sM[w];

        unsigned mA =  m        & 0xffu;
        unsigned mB = (m >> 8)  & 0xffu;
        unsigned mC = (m >> 16) & 0xffu;
        // argmax of a 0/1 vector = first set bit, or 0 if empty
        const int a = mA ? (__ffs(mA) - 1) : 0;
        const int b = mB ? (__ffs(mB) - 1) : 0;
        const int c = mC ? (__ffs(mC) - 1) : 0;

        const int task = min(max(sQ[1] - 49, 0), 3);

        float o[8];
        if (task == 3) {
            const float* tp = table + (((a * 8 + b) * 8 + c) * 8);
            #pragma unroll
            for (int k = 0; k < 8; k++) o[k] = __ldg(&tp[k]);
        } else {
            int idx;
            if (task == 0)      idx = a;                                     // copy
            else if (task == 1) idx = (a + 2 * b + 3 * c) & 7;               // affine
            else                idx = (a * (b + 1) + c * ((a ^ b) + 1)) & 7; // gate
            #pragma unroll
            for (int k = 0; k < 8; k++) o[k] = (k == idx) ? 12.0f : 0.0f;
        }

        float4* o4 = reinterpret_cast<float4*>(out + (size_t)row * 8);
        o4[0] = make_float4(o[0], o[1], o[2], o[3]);
        o4[1] = make_float4(o[4], o[5], o[6], o[7]);
    }
}

extern "C" void kernel_launch(void* const* d_in, const int* in_sizes, int n_in,
                              void* d_out, int out_size)
{
    const int* tok     = (const int*)d_in[0];     // token_ids [B, 4096] int32
    const float* table = (const float*)d_in[1];   // lookup_table [8,8,8,8] f32
    float* out         = (float*)d_out;           // [B, 8] f32

    const int B = in_sizes[0] / SEQ;
    tlc_kernel<<<B, TPB>>>(tok, table, out);
}

// round 5
// speedup vs baseline: 1.7960x; 1.2212x over previous
#include <cuda_runtime.h>

#define SEQ 4096
#define TPB 256
#define TOK 16
#define NW (TPB / 32)

__global__ __launch_bounds__(TPB, 8)
void tlc_kernel(const int* __restrict__ tok,
                const float* __restrict__ table,
                float* __restrict__ out)
{
    const int row  = blockIdx.x;
    const int* t   = tok + (size_t)row * SEQ;
    const int tid  = threadIdx.x;
    const int lane = tid & 31;
    const int wid  = tid >> 5;

    // query tag known up-front: uniform broadcast load of the row's last token
    const int qtag = min(max(__ldg(&t[SEQ - 1]) - 46, 0), 2);

    // ---- load my contiguous 16-token chunk (4 x int4)
    int arr[TOK];
    const int4* t4 = reinterpret_cast<const int4*>(t) + tid * 4;
    #pragma unroll
    for (int i = 0; i < 4; i++) {
        int4 v = t4[i];
        arr[4*i+0] = v.x; arr[4*i+1] = v.y;
        arr[4*i+2] = v.z; arr[4*i+3] = v.w;
    }
    const int tok1 = arr[1];   // t[1] lives in thread 0's registers

    // next chunk's first token: shfl for lanes 0..30, L1-hit ldg at warp boundary
    int nextFirst = __shfl_down_sync(0xffffffffu, arr[0], 1);
    if (lane == 31) nextFirst = (tid == TPB - 1) ? -1000000 : __ldg(&t[(tid + 1) * TOK]);

    // ---- single fused pass: tag tracking + dual-mask bigram match
    // candidate at (c,n): c in {3,4,5} and v = n+2-8c in [0,8); bit index u = n-22.
    // maskL: governed tag locally known and == qtag.  maskC: governed by carry (tag==-1).
    int tag = -1;
    unsigned mL = 0, mC = 0;
    #pragma unroll
    for (int i = 0; i < TOK; i++) {
        int c  = arr[i];
        int tt = c - 46;
        if ((unsigned)tt < 3u) tag = tt;                 // tag at pos p governs pos p
        int n = (i + 1 < TOK) ? arr[i + 1] : nextFirst;
        int v = n + 2 + c * (-8);                        // IMAD (fma pipe)
        unsigned u = (unsigned)(n - 22);
        bool cand = ((unsigned)(c - 3) < 3u) && ((unsigned)v < 8u);
        unsigned b = 1u << (u & 31u);
        if (cand && tag == qtag) mL |= b;
        if (cand && tag < 0)     mC |= b;
    }

    // ---- warp inclusive scan of chunk lastTag: combine(a,b) = (b>=0 ? b : a)
    int inc = tag;
    #pragma unroll
    for (int off = 1; off < 32; off <<= 1) {
        int p = __shfl_up_sync(0xffffffffu, inc, off);
        if (lane >= off && inc < 0) inc = p;
    }
    int excl = __shfl_up_sync(0xffffffffu, inc, 1);
    if (lane == 0) excl = -1;

    // resolve in-warp-known carries; collect still-pending carry masks
    unsigned m    = mL | ((excl == qtag) ? mC : 0u);     // excl==-1 never equals qtag
    unsigned pend = (excl < 0) ? mC : 0u;

    m    = __reduce_or_sync(0xffffffffu, m);
    pend = __reduce_or_sync(0xffffffffu, pend);
    const int wlast = __shfl_sync(0xffffffffu, inc, 31); // warp's last tag (or -1)

    __shared__ unsigned sM[NW], sP[NW];
    __shared__ int      sL[NW];
    if (lane == 0) { sM[wid] = m; sP[wid] = pend; sL[wid] = wlast; }
    __syncthreads();

    // ---- cross-warp resolve + epilogue: 8 threads of warp 0
    if (tid < NW) {
        unsigned mm = sM[tid], pp = sP[tid];
        int c2 = sL[tid];
        #pragma unroll
        for (int off = 1; off < NW; off <<= 1) {
            int p = __shfl_up_sync(0xffu, c2, off);
            if (tid >= off && c2 < 0) c2 = p;
        }
        int ex = __shfl_up_sync(0xffu, c2, 1);
        if (tid == 0) ex = -1;
        unsigned res = mm | ((ex == qtag) ? pp : 0u);
        res = __reduce_or_sync(0xffu, res);

        if (tid == 0) {
            unsigned mA =  res        & 0xffu;
            unsigned mB = (res >> 8)  & 0xffu;
            unsigned mCm= (res >> 16) & 0xffu;
            // argmax of 0/1 vector = first set bit, or 0 if empty
            const int a = mA  ? (__ffs(mA)  - 1) : 0;
            const int b = mB  ? (__ffs(mB)  - 1) : 0;
            const int c = mCm ? (__ffs(mCm) - 1) : 0;

            const int task = min(max(tok1 - 49, 0), 3);

            float o[8];
            if (task == 3) {
                const float* tp = table + (((a * 8 + b) * 8 + c) * 8);
                #pragma unroll
                for (int k = 0; k < 8; k++) o[k] = __ldg(&tp[k]);
            } else {
                int idx;
                if (task == 0)      idx = a;                                     // copy
                else if (task == 1) idx = (a + 2 * b + 3 * c) & 7;               // affine
                else                idx = (a * (b + 1) + c * ((a ^ b) + 1)) & 7; // gate
                #pragma unroll
                for (int k = 0; k < 8; k++) o[k] = (k == idx) ? 12.0f : 0.0f;
            }

            float4* o4 = reinterpret_cast<float4*>(out + (size_t)row * 8);
            o4[0] = make_float4(o[0], o[1], o[2], o[3]);
            o4[1] = make_float4(o[4], o[5], o[6], o[7]);
        }
    }
}

extern "C" void kernel_launch(void* const* d_in, const int* in_sizes, int n_in,
                              void* d_out, int out_size)
{
    const int* tok     = (const int*)d_in[0];     // token_ids [B, 4096] int32
    const float* table = (const float*)d_in[1];   // lookup_table [8,8,8,8] f32
    float* out         = (float*)d_out;           // [B, 8] f32

    const int B = in_sizes[0] / SEQ;
    tlc_kernel<<<B, TPB>>>(tok, table, out);
}

// round 6
// speedup vs baseline: 2.2432x; 1.2490x over previous
#include <cuda_runtime.h>

#define SEQ 4096
#define TPB 256
#define NW (TPB / 32)

__device__ __forceinline__ unsigned prmt(unsigned a, unsigned b, unsigned sel) {
    unsigned r;
    asm("prmt.b32 %0, %1, %2, %3;" : "=r"(r) : "r"(a), "r"(b), "r"(sel));
    return r;
}

__global__ __launch_bounds__(TPB)
void tlc_kernel(const int* __restrict__ tok,
                const float* __restrict__ table,
                float* __restrict__ out)
{
    const int row  = blockIdx.x;
    const int* t   = tok + (size_t)row * SEQ;
    const int tid  = threadIdx.x;
    const int lane = tid & 31;
    const int wid  = tid >> 5;

    // query tag known up-front (uniform broadcast load)
    const int qtag = min(max(__ldg(&t[SEQ - 1]) - 46, 0), 2);

    // ---- load my 16 tokens (4 x int4)
    const int4* t4 = reinterpret_cast<const int4*>(t) + tid * 4;
    int4 v0 = t4[0], v1 = t4[1], v2 = t4[2], v3 = t4[3];
    const int tok1 = v0.y;           // t[1] lives in thread 0

    // next chunk's first token (sentinel 0: never a value token, SWAR-safe)
    int nf = __shfl_down_sync(0xffffffffu, v0.x, 1);
    if (lane == 31) nf = (tid == TPB - 1) ? 0 : __ldg(&t[(tid + 1) * 16]);

    // ---- pack tokens (all <53, live in byte0 of each int32) into bytes
    unsigned P[4], N[4];
    {
        unsigned lo, hi;
        lo = prmt(v0.x, v0.y, 0x0040); hi = prmt(v0.z, v0.w, 0x4000);
        P[0] = prmt(lo, hi, 0x7610);
        lo = prmt(v1.x, v1.y, 0x0040); hi = prmt(v1.z, v1.w, 0x4000);
        P[1] = prmt(lo, hi, 0x7610);
        lo = prmt(v2.x, v2.y, 0x0040); hi = prmt(v2.z, v2.w, 0x4000);
        P[2] = prmt(lo, hi, 0x7610);
        lo = prmt(v3.x, v3.y, 0x0040); hi = prmt(v3.z, v3.w, 0x4000);
        P[3] = prmt(lo, hi, 0x7610);
    }
    N[0] = prmt(P[0], P[1], 0x4321);
    N[1] = prmt(P[1], P[2], 0x4321);
    N[2] = prmt(P[2], P[3], 0x4321);
    N[3] = prmt(P[3], (unsigned)nf, 0x4321);

    // ---- SWAR detection: per-byte bit7 flags, then movemask to 16-bit masks.
    // Valid because all token bytes < 128 (no cross-byte carries/borrows).
    unsigned tagpos = 0, candpos = 0;
    #pragma unroll
    for (int w = 0; w < 4; w++) {
        unsigned p = P[w], n = N[w];
        // tag bytes: (c-46) <u 3  -> bit7
        unsigned d1 = p + 0x52525252u;            // +(0x80-46)
        unsigned d2 = d1 - 0x03030303u;           // +(0x80-49)
        unsigned tm = (d1 & ~d2) & 0x80808080u;
        // role bytes: (c-3) <u 3 -> bit7
        unsigned r1 = p + 0x7D7D7D7Du;            // +(0x80-3)
        unsigned r2 = r1 - 0x03030303u;           // +(0x80-6)
        unsigned rm = (r1 & ~r2) & 0x80808080u;
        // 8c on role bytes only (mask prevents SWAR borrows from junk bytes)
        unsigned c8  = (p << 3) & 0xF8F8F8F8u;
        unsigned c8r = c8 & ((rm >> 7) * 0xF8u);
        // value window: (n + 2 - 8c) in [0,8)  -> bit7
        unsigned e1 = (n + 0x82828282u) - c8r;    // bit7 iff n+2-8c >= 0
        unsigned e2 = e1 - 0x08080808u;           // bit7 iff n+2-8c >= 8
        unsigned cm = (e1 & ~e2) & rm;
        tagpos  |= ((tm * 0x00204081u) >> 28) << (4 * w);
        candpos |= ((cm * 0x00204081u) >> 28) << (4 * w);
    }

    // ---- chunk lastTag from msb of tagpos (no serial per-token chain)
    int lastTag = -1;
    if (tagpos) {
        int j = 31 - __clz(tagpos);
        unsigned pw = (j & 8) ? ((j & 4) ? P[3] : P[2])
                              : ((j & 4) ? P[1] : P[0]);
        lastTag = (int)(prmt(pw, 0u, (unsigned)(j & 3)) & 0xFFu) - 46;
    }

    // ---- rare path: resolve each candidate's governing tag
    unsigned mL = 0, mC = 0;
    while (candpos) {
        int k = __ffs(candpos) - 1;
        candpos &= candpos - 1;
        unsigned nw = (k & 8) ? ((k & 4) ? N[3] : N[2])
                              : ((k & 4) ? N[1] : N[0]);
        unsigned u  = (prmt(nw, 0u, (unsigned)(k & 3)) & 0xFFu) - 22u;  // bit index 0..23
        unsigned bit = 1u << u;
        unsigned tb = tagpos & ((2u << k) - 1u);   // in-thread tags at <= k
        if (tb) {
            int j = 31 - __clz(tb);
            unsigned pw = (j & 8) ? ((j & 4) ? P[3] : P[2])
                                  : ((j & 4) ? P[1] : P[0]);
            int tv = (int)(prmt(pw, 0u, (unsigned)(j & 3)) & 0xFFu) - 46;
            if (tv == qtag) mL |= bit;
        } else {
            mC |= bit;                              // governed by carry tag
        }
    }

    // ---- warp inclusive scan of lastTag: combine(a,b) = (b>=0 ? b : a)
    int inc = lastTag;
    #pragma unroll
    for (int off = 1; off < 32; off <<= 1) {
        int p = __shfl_up_sync(0xffffffffu, inc, off);
        if (lane >= off && inc < 0) inc = p;
    }
    int excl = __shfl_up_sync(0xffffffffu, inc, 1);
    if (lane == 0) excl = -1;

    unsigned m    = mL | ((excl == qtag) ? mC : 0u);
    unsigned pend = (excl < 0) ? mC : 0u;

    m    = __reduce_or_sync(0xffffffffu, m);
    pend = __reduce_or_sync(0xffffffffu, pend);
    const int wlast = __shfl_sync(0xffffffffu, inc, 31);

    __shared__ unsigned sM[NW], sP[NW];
    __shared__ int      sL[NW];
    if (lane == 0) { sM[wid] = m; sP[wid] = pend; sL[wid] = wlast; }
    __syncthreads();

    // ---- cross-warp resolve + epilogue (8 threads of warp 0)
    if (tid < NW) {
        unsigned mm = sM[tid], pp = sP[tid];
        int c2 = sL[tid];
        #pragma unroll
        for (int off = 1; off < NW; off <<= 1) {
            int p = __shfl_up_sync(0xffu, c2, off);
            if (tid >= off && c2 < 0) c2 = p;
        }
        int ex = __shfl_up_sync(0xffu, c2, 1);
        if (tid == 0) ex = -1;
        unsigned res = mm | ((ex == qtag) ? pp : 0u);
        res = __reduce_or_sync(0xffu, res);

        if (tid == 0) {
            unsigned mA  =  res        & 0xffu;
            unsigned mB  = (res >> 8)  & 0xffu;
            unsigned mCm = (res >> 16) & 0xffu;
            const int a = mA  ? (__ffs(mA)  - 1) : 0;
            const int b = mB  ? (__ffs(mB)  - 1) : 0;
            const int c = mCm ? (__ffs(mCm) - 1) : 0;

            const int task = min(max(tok1 - 49, 0), 3);

            float o[8];
            if (task == 3) {
                const float* tp = table + (((a * 8 + b) * 8 + c) * 8);
                #pragma unroll
                for (int k = 0; k < 8; k++) o[k] = __ldg(&tp[k]);
            } else {
                int idx;
                if (task == 0)      idx = a;
                else if (task == 1) idx = (a + 2 * b + 3 * c) & 7;
                else                idx = (a * (b + 1) + c * ((a ^ b) + 1)) & 7;
                #pragma unroll
                for (int k = 0; k < 8; k++) o[k] = (k == idx) ? 12.0f : 0.0f;
            }

            float4* o4 = reinterpret_cast<float4*>(out + (size_t)row * 8);
            o4[0] = make_float4(o[0], o[1], o[2], o[3]);
            o4[1] = make_float4(o[4], o[5], o[6], o[7]);
        }
    }
}

extern "C" void kernel_launch(void* const* d_in, const int* in_sizes, int n_in,
                              void* d_out, int out_size)
{
    const int* tok     = (const int*)d_in[0];     // token_ids [B, 4096] int32
    const float* table = (const float*)d_in[1];   // lookup_table [8,8,8,8] f32
    float* out         = (float*)d_out;           // [B, 8] f32

    const int B = in_sizes[0] / SEQ;
    tlc_kernel<<<B, TPB>>>(tok, table, out);
}

// round 7
// speedup vs baseline: 2.2520x; 1.0039x over previous
#include <cuda_runtime.h>

#define SEQ 4096
#define TPB 256
#define NW (TPB / 32)

__device__ __forceinline__ unsigned prmt(unsigned a, unsigned b, unsigned sel) {
    unsigned r;
    asm("prmt.b32 %0, %1, %2, %3;" : "=r"(r) : "r"(a), "r"(b), "r"(sel));
    return r;
}

__global__ __launch_bounds__(TPB)
void tlc_kernel(const int* __restrict__ tok,
                const float* __restrict__ table,
                float* __restrict__ out)
{
    const int row  = blockIdx.x;
    const int* t   = tok + (size_t)row * SEQ;
    const int tid  = threadIdx.x;
    const int lane = tid & 31;
    const int wid  = tid >> 5;

    __shared__ unsigned sTok[SEQ / 4];          // whole row, byte-packed (4 KB)
    __shared__ unsigned sM[NW], sP[NW];
    __shared__ int      sL[NW];

    // ---- coalesced load + immediate byte-pack + smem stage
    // segment = one int4 = 4 consecutive tokens; lane l takes segments w*128+32i+l
    const int4* t4 = reinterpret_cast<const int4*>(t);
    const int base = wid * 128 + lane;
    #pragma unroll
    for (int i = 0; i < 4; i++) {
        int4 v = t4[base + 32 * i];             // warp-consecutive -> 4 lines/LDG
        unsigned lo = prmt(v.x, v.y, 0x0040);
        unsigned hi = prmt(v.z, v.w, 0x4000);
        sTok[base + 32 * i] = prmt(lo, hi, 0x7610);
    }
    __syncthreads();

    // thread's contiguous 16 tokens as 4 packed words (single conflict-free LDS.128)
    unsigned P[4];
    *reinterpret_cast<uint4*>(P) = *reinterpret_cast<const uint4*>(&sTok[tid * 4]);

    // query tag: last token of row = byte3 of last packed word (broadcast LDS)
    const int qtag = min(max((int)(sTok[SEQ / 4 - 1] >> 24) - 46, 0), 2);

    // next chunk's first packed word (byte0 = boundary token); sentinel 0 at row end
    unsigned nfw = __shfl_down_sync(0xffffffffu, P[0], 1);
    if (lane == 31) nfw = (tid == TPB - 1) ? 0u : sTok[tid * 4 + 4];

    unsigned N[4];
    N[0] = prmt(P[0], P[1], 0x4321);
    N[1] = prmt(P[1], P[2], 0x4321);
    N[2] = prmt(P[2], P[3], 0x4321);
    N[3] = prmt(P[3], nfw,  0x4321);

    // ---- SWAR detection: per-byte bit7 flags, movemask to 16-bit position masks.
    // Valid because all token bytes < 128 (no cross-byte carries/borrows).
    unsigned tagpos = 0, candpos = 0;
    #pragma unroll
    for (int w = 0; w < 4; w++) {
        unsigned p = P[w], n = N[w];
        // tag bytes: (c-46) <u 3 -> bit7
        unsigned d1 = p + 0x52525252u;
        unsigned d2 = d1 - 0x03030303u;
        unsigned tm = (d1 & ~d2) & 0x80808080u;
        // role bytes: (c-3) <u 3 -> bit7
        unsigned r1 = p + 0x7D7D7D7Du;
        unsigned r2 = r1 - 0x03030303u;
        unsigned rm = (r1 & ~r2) & 0x80808080u;
        // 8c on role bytes only (mask prevents SWAR borrows from junk bytes)
        unsigned c8  = (p << 3) & 0xF8F8F8F8u;
        unsigned c8r = c8 & ((rm >> 7) * 0xF8u);
        // value window: (n + 2 - 8c) in [0,8) -> bit7
        unsigned e1 = (n + 0x82828282u) - c8r;
        unsigned e2 = e1 - 0x08080808u;
        unsigned cm = (e1 & ~e2) & rm;
        tagpos  |= ((tm * 0x00204081u) >> 28) << (4 * w);
        candpos |= ((cm * 0x00204081u) >> 28) << (4 * w);
    }

    // ---- chunk lastTag from msb of tagpos
    int lastTag = -1;
    if (tagpos) {
        int j = 31 - __clz(tagpos);
        unsigned pw = (j & 8) ? ((j & 4) ? P[3] : P[2])
                              : ((j & 4) ? P[1] : P[0]);
        lastTag = (int)(prmt(pw, 0u, (unsigned)(j & 3)) & 0xFFu) - 46;
    }

    // ---- rare path: resolve each candidate's governing tag
    unsigned mL = 0, mC = 0;
    while (candpos) {
        int k = __ffs(candpos) - 1;
        candpos &= candpos - 1;
        unsigned nw = (k & 8) ? ((k & 4) ? N[3] : N[2])
                              : ((k & 4) ? N[1] : N[0]);
        unsigned u  = (prmt(nw, 0u, (unsigned)(k & 3)) & 0xFFu) - 22u;  // bit 0..23
        unsigned bit = 1u << u;
        unsigned tb = tagpos & ((2u << k) - 1u);   // in-thread tags at pos <= k
        if (tb) {
            int j = 31 - __clz(tb);
            unsigned pw = (j & 8) ? ((j & 4) ? P[3] : P[2])
                                  : ((j & 4) ? P[1] : P[0]);
            int tv = (int)(prmt(pw, 0u, (unsigned)(j & 3)) & 0xFFu) - 46;
            if (tv == qtag) mL |= bit;
        } else {
            mC |= bit;                              // governed by carry tag
        }
    }

    // ---- warp inclusive scan of lastTag: combine(a,b) = (b>=0 ? b : a)
    int inc = lastTag;
    #pragma unroll
    for (int off = 1; off < 32; off <<= 1) {
        int p = __shfl_up_sync(0xffffffffu, inc, off);
        if (lane >= off && inc < 0) inc = p;
    }
    int excl = __shfl_up_sync(0xffffffffu, inc, 1);
    if (lane == 0) excl = -1;

    unsigned m    = mL | ((excl == qtag) ? mC : 0u);
    unsigned pend = (excl < 0) ? mC : 0u;

    m    = __reduce_or_sync(0xffffffffu, m);
    pend = __reduce_or_sync(0xffffffffu, pend);
    const int wlast = __shfl_sync(0xffffffffu, inc, 31);

    if (lane == 0) { sM[wid] = m; sP[wid] = pend; sL[wid] = wlast; }
    __syncthreads();

    // ---- cross-warp resolve + epilogue (8 threads of warp 0)
    if (tid < NW) {
        unsigned mm = sM[tid], pp = sP[tid];
        int c2 = sL[tid];
        #pragma unroll
        for (int off = 1; off < NW; off <<= 1) {
            int p = __shfl_up_sync(0xffu, c2, off);
            if (tid >= off && c2 < 0) c2 = p;
        }
        int ex = __shfl_up_sync(0xffu, c2, 1);
        if (tid == 0) ex = -1;
        unsigned res = mm | ((ex == qtag) ? pp : 0u);
        res = __reduce_or_sync(0xffu, res);

        if (tid == 0) {
            unsigned mA  =  res        & 0xffu;
            unsigned mB  = (res >> 8)  & 0xffu;
            unsigned mCm = (res >> 16) & 0xffu;
            const int a = mA  ? (__ffs(mA)  - 1) : 0;
            const int b = mB  ? (__ffs(mB)  - 1) : 0;
            const int c = mCm ? (__ffs(mCm) - 1) : 0;

            const int task = min(max((int)((sTok[0] >> 8) & 0xFFu) - 49, 0), 3);

            float o[8];
            if (task == 3) {
                const float* tp = table + (((a * 8 + b) * 8 + c) * 8);
                #pragma unroll
                for (int k = 0; k < 8; k++) o[k] = __ldg(&tp[k]);
            } else {
                int idx;
                if (task == 0)      idx = a;
                else if (task == 1) idx = (a + 2 * b + 3 * c) & 7;
                else                idx = (a * (b + 1) + c * ((a ^ b) + 1)) & 7;
                #pragma unroll
                for (int k = 0; k < 8; k++) o[k] = (k == idx) ? 12.0f : 0.0f;
            }

            float4* o4 = reinterpret_cast<float4*>(out + (size_t)row * 8);
            o4[0] = make_float4(o[0], o[1], o[2], o[3]);
            o4[1] = make_float4(o[4], o[5], o[6], o[7]);
        }
    }
}

extern "C" void kernel_launch(void* const* d_in, const int* in_sizes, int n_in,
                              void* d_out, int out_size)
{
    const int* tok     = (const int*)d_in[0];     // token_ids [B, 4096] int32
    const float* table = (const float*)d_in[1];   // lookup_table [8,8,8,8] f32
    float* out         = (float*)d_out;           // [B, 8] f32

    const int B = in_sizes[0] / SEQ;
    tlc_kernel<<<B, TPB>>>(tok, table, out);
}